// round 2
// baseline (speedup 1.0000x reference)
#include <cuda_runtime.h>
#include <cstdint>

#define NB 2
#define NT 2048
#define NC 1024
#define NH 16
#define DH 64

// fp32 scratch (device globals: no allocation in kernel_launch)
__device__ float g_q[NB * NH * NT * DH];
__device__ float g_k[NB * NH * NT * DH];
__device__ float g_v[NB * NH * NT * DH];
__device__ float g_y[NB * NT * NC];

__device__ __forceinline__ uint32_t f2t(float f) {
    uint32_t u;
    asm("cvt.rna.tf32.f32 %0, %1;" : "=r"(u) : "f"(f));
    return u;
}

__device__ __forceinline__ void mma8(float d[4], const uint32_t a[4],
                                     uint32_t b0, uint32_t b1) {
    asm volatile(
        "mma.sync.aligned.m16n8k8.row.col.f32.tf32.tf32.f32 "
        "{%0,%1,%2,%3}, {%4,%5,%6,%7}, {%8,%9}, {%0,%1,%2,%3};\n"
        : "+f"(d[0]), "+f"(d[1]), "+f"(d[2]), "+f"(d[3])
        : "r"(a[0]), "r"(a[1]), "r"(a[2]), "r"(a[3]), "r"(b0), "r"(b1));
}

// ---------------------------------------------------------------------------
// tf32 GEMM, fragment-major smem, double-buffered, reg-prefetch pipeline.
// Block 256 threads (8 warps, 2x4), tile 128x128, BK=32.
// Smem (dynamic 64KB):
//   Asf[buf][wm][kk][mi][perm-lane][e]  (uint4 per lane)
//   Bsf[buf][wn][kk][ni][perm-lane][bi] (uint2 per lane)
// MODE 0: QKV projection, scatter epilogue into g_k/g_q/g_v (q scaled 0.125).
// MODE 1: output projection (A = g_y), fp32 out + bias.
// ---------------------------------------------------------------------------
template <int MODE>
__global__ __launch_bounds__(256) void gemm_k(const float* __restrict__ A,
                                              const float* __restrict__ W,
                                              const float* __restrict__ bias,
                                              float* __restrict__ out,
                                              int K, int N) {
    extern __shared__ __align__(16) uint32_t smem[];
    uint32_t* Asf = smem;            // 2 x 4096
    uint32_t* Bsf = smem + 8192;     // 2 x 4096
    const float* Ap = (MODE == 1) ? g_y : A;

    int tid = threadIdx.x;
    int warp = tid >> 5, lane = tid & 31;
    int wm = warp >> 2, wn = warp & 3;       // 2 x 4 warp grid
    int m0 = blockIdx.y * 128, n0 = blockIdx.x * 128;

    float acc[4][4][4];
#pragma unroll
    for (int mi = 0; mi < 4; mi++)
#pragma unroll
        for (int ni = 0; ni < 4; ni++)
#pragma unroll
            for (int e = 0; e < 4; e++) acc[mi][ni][e] = 0.0f;

    float4 ra[4], rb[4];

    // ---- load tile 0
#pragma unroll
    for (int p = 0; p < 4; p++) {
        int idx = tid + p * 256;
        int r = idx >> 3, c0 = (idx & 7) * 4;
        ra[p] = *(const float4*)(Ap + (size_t)(m0 + r) * K + c0);
    }
#pragma unroll
    for (int p = 0; p < 4; p++) {
        int idx = tid + p * 256;
        int r = idx >> 5, c0 = (idx & 31) * 4;
        rb[p] = *(const float4*)(W + (size_t)r * N + n0 + c0);
    }

    int buf = 0;
    // ---- scatter tile 0 into buf0
#pragma unroll
    for (int p = 0; p < 4; p++) {
        int idx = tid + p * 256;
        int r = idx >> 3, c0 = (idx & 7) * 4;
        int wmi = r >> 6, mi = (r >> 4) & 3, gg = r & 7, half = (r >> 3) & 1;
        float v[4] = {ra[p].x, ra[p].y, ra[p].z, ra[p].w};
#pragma unroll
        for (int i = 0; i < 4; i++) {
            int k = c0 + i;
            int kk = k >> 3, tt = k & 3, ch = (k >> 2) & 1;
            int e = half + 2 * ch;
            int perm = (gg * 4 + tt) ^ (kk * 5);
            Asf[(((wmi * 4 + kk) * 4 + mi) * 32 + perm) * 4 + e] = f2t(v[i]);
        }
    }
#pragma unroll
    for (int p = 0; p < 4; p++) {
        int idx = tid + p * 256;
        int r = idx >> 5, c0 = (idx & 31) * 4;
        int kk = r >> 3, tb = r & 3, bi = (r >> 2) & 1;
        float v[4] = {rb[p].x, rb[p].y, rb[p].z, rb[p].w};
#pragma unroll
        for (int i = 0; i < 4; i++) {
            int c = c0 + i;
            int wnn = c >> 5, ni = (c >> 3) & 3, gb = c & 7;
            int perm = (gb * 4 + tb) ^ (wnn * 4 + ni);
            Bsf[(((wnn * 4 + kk) * 4 + ni) * 32 + perm) * 2 + bi] = f2t(v[i]);
        }
    }
    __syncthreads();

    int ntiles = K >> 5;
    for (int kt = 0; kt < ntiles; kt++) {
        bool more = (kt + 1 < ntiles);
        // ---- prefetch next tile into regs
        if (more) {
            int koff = (kt + 1) * 32;
#pragma unroll
            for (int p = 0; p < 4; p++) {
                int idx = tid + p * 256;
                int r = idx >> 3, c0 = (idx & 7) * 4;
                ra[p] = *(const float4*)(Ap + (size_t)(m0 + r) * K + koff + c0);
            }
#pragma unroll
            for (int p = 0; p < 4; p++) {
                int idx = tid + p * 256;
                int r = idx >> 5, c0 = (idx & 31) * 4;
                rb[p] = *(const float4*)(W + (size_t)(koff + r) * N + n0 + c0);
            }
        }
        // ---- compute from current buffer
        const uint32_t* Ab = Asf + buf * 4096;
        const uint32_t* Bb = Bsf + buf * 4096;
#pragma unroll
        for (int kk = 0; kk < 4; kk++) {
            int pa = lane ^ (kk * 5);
            uint4 a[4];
#pragma unroll
            for (int mi = 0; mi < 4; mi++)
                a[mi] = *(const uint4*)&Ab[(((wm * 4 + kk) * 4 + mi) * 32 + pa) * 4];
            uint2 b[4];
#pragma unroll
            for (int ni = 0; ni < 4; ni++) {
                int pb = lane ^ (wn * 4 + ni);
                b[ni] = *(const uint2*)&Bb[(((wn * 4 + kk) * 4 + ni) * 32 + pb) * 2];
            }
#pragma unroll
            for (int mi = 0; mi < 4; mi++)
#pragma unroll
                for (int ni = 0; ni < 4; ni++)
                    mma8(acc[mi][ni], (const uint32_t*)&a[mi], b[ni].x, b[ni].y);
        }
        // ---- scatter prefetched tile into other buffer
        if (more) {
            uint32_t* Aw = Asf + (buf ^ 1) * 4096;
            uint32_t* Bw = Bsf + (buf ^ 1) * 4096;
#pragma unroll
            for (int p = 0; p < 4; p++) {
                int idx = tid + p * 256;
                int r = idx >> 3, c0 = (idx & 7) * 4;
                int wmi = r >> 6, mi = (r >> 4) & 3, gg = r & 7, half = (r >> 3) & 1;
                float v[4] = {ra[p].x, ra[p].y, ra[p].z, ra[p].w};
#pragma unroll
                for (int i = 0; i < 4; i++) {
                    int k = c0 + i;
                    int kk = k >> 3, tt = k & 3, ch = (k >> 2) & 1;
                    int e = half + 2 * ch;
                    int perm = (gg * 4 + tt) ^ (kk * 5);
                    Aw[(((wmi * 4 + kk) * 4 + mi) * 32 + perm) * 4 + e] = f2t(v[i]);
                }
            }
#pragma unroll
            for (int p = 0; p < 4; p++) {
                int idx = tid + p * 256;
                int r = idx >> 5, c0 = (idx & 31) * 4;
                int kk = r >> 3, tb = r & 3, bi = (r >> 2) & 1;
                float v[4] = {rb[p].x, rb[p].y, rb[p].z, rb[p].w};
#pragma unroll
                for (int i = 0; i < 4; i++) {
                    int c = c0 + i;
                    int wnn = c >> 5, ni = (c >> 3) & 3, gb = c & 7;
                    int perm = (gb * 4 + tb) ^ (wnn * 4 + ni);
                    Bw[(((wnn * 4 + kk) * 4 + ni) * 32 + perm) * 2 + bi] = f2t(v[i]);
                }
            }
        }
        __syncthreads();
        buf ^= 1;
    }

    // Epilogue. C frag: c0=(g, 2t), c1=(g, 2t+1), c2=(g+8, 2t), c3=(g+8, 2t+1)
    int g = lane >> 2, t = lane & 3;
#pragma unroll
    for (int mi = 0; mi < 4; mi++)
#pragma unroll
        for (int ni = 0; ni < 4; ni++)
#pragma unroll
            for (int e = 0; e < 4; e++) {
                int m = m0 + wm * 64 + mi * 16 + g + ((e >= 2) ? 8 : 0);
                int n = n0 + wn * 32 + ni * 8 + t * 2 + (e & 1);
                float val = acc[mi][ni][e] + bias[n];
                if (MODE == 0) {
                    int b = m >> 11, tt = m & (NT - 1);
                    int head = n / 192;
                    int r = n - head * 192;
                    int kind = r >> 6, d = r & 63;   // split order: k, q, v
                    size_t idx = ((size_t)(b * NH + head) * NT + tt) * DH + d;
                    if (kind == 0)      g_k[idx] = val;
                    else if (kind == 1) g_q[idx] = val * 0.125f;  // fold scale
                    else                g_v[idx] = val;
                } else {
                    out[(size_t)m * NC + n] = val;
                }
            }
}

// ---------------------------------------------------------------------------
// Causal flash attention. Grid (T/64, B*H), block 128 (4 warps).
// Each warp owns 16 query rows; 64-key tiles staged as tf32 fragments in smem.
// ---------------------------------------------------------------------------
__global__ __launch_bounds__(128) void attn_k() {
    __shared__ __align__(16) uint32_t Kf[4096];  // [kk(8)][j(8)][perm-lane][bi]
    __shared__ __align__(16) uint32_t Vf[4096];  // [kk(8)][jd(8)][perm-lane][bi]

    int tid = threadIdx.x, w = tid >> 5, lane = tid & 31;
    int g = lane >> 2, t = lane & 3;
    int bh = blockIdx.y;
    int qb = blockIdx.x;                       // 64-row query tile index
    size_t base = (size_t)bh * NT * DH;
    int r0 = qb * 64 + w * 16;                 // warp's first query row

    // Load Q fragments once (q already scaled by 1/sqrt(hd))
    uint32_t qf[8][4];
    const float* qp = g_q + base + (size_t)r0 * DH;
#pragma unroll
    for (int kk = 0; kk < 8; kk++) {
        qf[kk][0] = f2t(qp[g * DH + kk * 8 + t]);
        qf[kk][1] = f2t(qp[(g + 8) * DH + kk * 8 + t]);
        qf[kk][2] = f2t(qp[g * DH + kk * 8 + t + 4]);
        qf[kk][3] = f2t(qp[(g + 8) * DH + kk * 8 + t + 4]);
    }

    float o[8][4];
#pragma unroll
    for (int jd = 0; jd < 8; jd++)
#pragma unroll
        for (int e = 0; e < 4; e++) o[jd][e] = 0.0f;
    float mrow[2] = {-1e30f, -1e30f};
    float lrow[2] = {0.0f, 0.0f};

    const unsigned FULL = 0xffffffffu;
    int s1 = (lane & ~3) | (t >> 1);   // src lane for P col t
    int s2 = s1 + 2;                   // src lane for P col t+4

    for (int kt = 0; kt <= qb; kt++) {
        __syncthreads();
        const float* kp = g_k + base + (size_t)kt * 64 * DH;
        const float* vp = g_v + base + (size_t)kt * 64 * DH;
#pragma unroll
        for (int p = 0; p < 8; p++) {
            int idx = tid + p * 128;
            int r = idx >> 4, c0 = (idx & 15) * 4;
            float4 k4 = *(const float4*)(kp + r * DH + c0);
            float4 v4 = *(const float4*)(vp + r * DH + c0);
            // K scatter: element (row=r, d=c0+i)
            int j = r >> 3, gk = r & 7;
            float kv[4] = {k4.x, k4.y, k4.z, k4.w};
            float vv[4] = {v4.x, v4.y, v4.z, v4.w};
#pragma unroll
            for (int i = 0; i < 4; i++) {
                int d = c0 + i;
                int kk = d >> 3, tk = d & 3, bik = (d >> 2) & 1;
                int perm = (gk * 4 + tk) ^ ((kk * 5) & 15);
                Kf[((kk * 8 + j) * 32 + perm) * 2 + bik] = f2t(kv[i]);
            }
            // V scatter: element (row=r, c=c0+i)
            int kkv = r >> 3, rc = r & 7;
            int tv = rc & 3, biv = rc >> 2;
#pragma unroll
            for (int i = 0; i < 4; i++) {
                int c = c0 + i;
                int jd = c >> 3, gv = c & 7;
                int perm = (gv * 4 + tv) ^ jd;
                Vf[((kkv * 8 + jd) * 32 + perm) * 2 + biv] = f2t(vv[i]);
            }
        }
        __syncthreads();

        // S = Q K^T
        float s[8][4];
#pragma unroll
        for (int j = 0; j < 8; j++)
#pragma unroll
            for (int e = 0; e < 4; e++) s[j][e] = 0.0f;
#pragma unroll
        for (int kk = 0; kk < 8; kk++) {
            int pk = lane ^ ((kk * 5) & 15);
#pragma unroll
            for (int j = 0; j < 8; j++) {
                uint2 b = *(const uint2*)&Kf[((kk * 8 + j) * 32 + pk) * 2];
                mma8(s[j], qf[kk], b.x, b.y);
            }
        }

        // Causal mask: only the diagonal tile is partial
        if (kt == qb) {
#pragma unroll
            for (int j = 0; j < 8; j++) {
                int key = kt * 64 + j * 8 + t * 2;
                if (key > r0 + g)         s[j][0] = -1e30f;
                if (key + 1 > r0 + g)     s[j][1] = -1e30f;
                if (key > r0 + g + 8)     s[j][2] = -1e30f;
                if (key + 1 > r0 + g + 8) s[j][3] = -1e30f;
            }
        }

        // Online softmax per row-half (rows g and g+8)
#pragma unroll
        for (int h2 = 0; h2 < 2; h2++) {
            float tm = -1e30f;
#pragma unroll
            for (int j = 0; j < 8; j++)
                tm = fmaxf(tm, fmaxf(s[j][h2 * 2], s[j][h2 * 2 + 1]));
            tm = fmaxf(tm, __shfl_xor_sync(FULL, tm, 1));
            tm = fmaxf(tm, __shfl_xor_sync(FULL, tm, 2));
            float nm = fmaxf(mrow[h2], tm);
            float corr = __expf(mrow[h2] - nm);
            mrow[h2] = nm;
            float sum = 0.0f;
#pragma unroll
            for (int j = 0; j < 8; j++) {
                float p0 = __expf(s[j][h2 * 2] - nm);
                float p1 = __expf(s[j][h2 * 2 + 1] - nm);
                s[j][h2 * 2] = p0; s[j][h2 * 2 + 1] = p1;
                sum += p0 + p1;
            }
            sum += __shfl_xor_sync(FULL, sum, 1);
            sum += __shfl_xor_sync(FULL, sum, 2);
            lrow[h2] = lrow[h2] * corr + sum;
#pragma unroll
            for (int jd = 0; jd < 8; jd++) {
                o[jd][h2 * 2] *= corr;
                o[jd][h2 * 2 + 1] *= corr;
            }
        }

        // O += P V : re-fragment P (C-layout cols 2t,2t+1 -> A-layout cols t,t+4)
        bool odd = (t & 1);
#pragma unroll
        for (int kk = 0; kk < 8; kk++) {
            float c0 = s[kk][0], c1 = s[kk][1], c2 = s[kk][2], c3 = s[kk][3];
            float v0a = __shfl_sync(FULL, c0, s1), v0b = __shfl_sync(FULL, c1, s1);
            float v1a = __shfl_sync(FULL, c2, s1), v1b = __shfl_sync(FULL, c3, s1);
            float v2a = __shfl_sync(FULL, c0, s2), v2b = __shfl_sync(FULL, c1, s2);
            float v3a = __shfl_sync(FULL, c2, s2), v3b = __shfl_sync(FULL, c3, s2);
            uint32_t pa[4];
            pa[0] = f2t(odd ? v0b : v0a);
            pa[1] = f2t(odd ? v1b : v1a);
            pa[2] = f2t(odd ? v2b : v2a);
            pa[3] = f2t(odd ? v3b : v3a);
#pragma unroll
            for (int jd = 0; jd < 8; jd++) {
                int pv = lane ^ jd;
                uint2 b = *(const uint2*)&Vf[((kk * 8 + jd) * 32 + pv) * 2];
                mma8(o[jd], pa, b.x, b.y);
            }
        }
    }

    // Normalize and write y[b, t, h*64+d]
    int b = bh >> 4, head = bh & 15;
    float inv0 = 1.0f / lrow[0], inv1 = 1.0f / lrow[1];
#pragma unroll
    for (int jd = 0; jd < 8; jd++) {
        int d = head * 64 + jd * 8 + t * 2;
        float* y0 = g_y + (size_t)(b * NT + r0 + g) * NC + d;
        float* y1 = g_y + (size_t)(b * NT + r0 + g + 8) * NC + d;
        y0[0] = o[jd][0] * inv0; y0[1] = o[jd][1] * inv0;
        y1[0] = o[jd][2] * inv1; y1[1] = o[jd][3] * inv1;
    }
}

// ---------------------------------------------------------------------------
extern "C" void kernel_launch(void* const* d_in, const int* in_sizes, int n_in,
                              void* d_out, int out_size) {
    (void)in_sizes; (void)n_in; (void)out_size;
    const float* x      = (const float*)d_in[0];
    // d_in[1] = att_mask: causal tril by construction; masking is hardcoded.
    const float* w_kqv  = (const float*)d_in[2];
    const float* b_kqv  = (const float*)d_in[3];
    const float* w_proj = (const float*)d_in[4];
    const float* b_proj = (const float*)d_in[5];
    float* out = (float*)d_out;

    static int attr_set = 0;
    if (!attr_set) {
        cudaFuncSetAttribute(gemm_k<0>, cudaFuncAttributeMaxDynamicSharedMemorySize, 65536);
        cudaFuncSetAttribute(gemm_k<1>, cudaFuncAttributeMaxDynamicSharedMemorySize, 65536);
        attr_set = 1;
    }

    // 1) kqv = x @ w_kqv + b, scattered to K/Q/V scratch (q pre-scaled)
    gemm_k<0><<<dim3(24, 32), 256, 65536>>>(x, w_kqv, b_kqv, nullptr, NC, 3 * NC);
    // 2) causal flash attention -> g_y
    attn_k<<<dim3(NT / 64, NB * NH), 128>>>();
    // 3) out = y @ w_proj + b
    gemm_k<1><<<dim3(8, 32), 256, 65536>>>(nullptr, w_proj, b_proj, out, NC, NC);
}

// round 5
// speedup vs baseline: 1.2675x; 1.2675x over previous
#include <cuda_runtime.h>
#include <cstdint>

#define NB 2
#define NT 2048
#define NC 1024
#define NH 16
#define DH 64

// fp32 scratch (device globals: no allocation in kernel_launch)
__device__ __align__(16) float g_q[NB * NH * NT * DH];
__device__ __align__(16) float g_k[NB * NH * NT * DH];
__device__ __align__(16) float g_v[NB * NH * NT * DH];
__device__ __align__(16) float g_y[NB * NT * NC];
__device__ __align__(16) float g_x[NB * NT * NC];      // tf32-rounded x
__device__ __align__(16) float g_wk[3 * NC * NC];      // tf32-rounded w_kqv [1024,3072]
__device__ __align__(16) float g_wp[NC * NC];          // tf32-rounded w_proj [1024,1024]

__device__ __forceinline__ uint32_t f2t(float f) {
    uint32_t u;
    asm("cvt.rna.tf32.f32 %0, %1;" : "=r"(u) : "f"(f));
    return u;
}

__device__ __forceinline__ uint32_t smem_u32(const void* p) {
    uint32_t a;
    asm("{ .reg .u64 t; cvta.to.shared.u64 t, %1; cvt.u32.u64 %0, t; }"
        : "=r"(a) : "l"(p));
    return a;
}

__device__ __forceinline__ void cp16(uint32_t dst, const void* src) {
    asm volatile("cp.async.cg.shared.global [%0], [%1], 16;\n" :: "r"(dst), "l"(src));
}
__device__ __forceinline__ void cp_commit() {
    asm volatile("cp.async.commit_group;\n" ::: "memory");
}
template <int N>
__device__ __forceinline__ void cp_wait() {
    asm volatile("cp.async.wait_group %0;\n" :: "n"(N) : "memory");
}

__device__ __forceinline__ void mma8(float d[4], const uint32_t a[4],
                                     uint32_t b0, uint32_t b1) {
    asm volatile(
        "mma.sync.aligned.m16n8k8.row.col.f32.tf32.tf32.f32 "
        "{%0,%1,%2,%3}, {%4,%5,%6,%7}, {%8,%9}, {%0,%1,%2,%3};\n"
        : "+f"(d[0]), "+f"(d[1]), "+f"(d[2]), "+f"(d[3])
        : "r"(a[0]), "r"(a[1]), "r"(a[2]), "r"(a[3]), "r"(b0), "r"(b1));
}

// ---------------------------------------------------------------------------
// Prep: round tensors to tf32 bit patterns (raw bits then valid mma operands).
// T=0: x -> g_x ; T=1: w_kqv -> g_wk ; T=2: w_proj -> g_wp
// ---------------------------------------------------------------------------
template <int T>
__global__ void round_k(const float4* __restrict__ in) {
    float4* outp = (T == 0) ? (float4*)g_x : (T == 1) ? (float4*)g_wk : (float4*)g_wp;
    int i = blockIdx.x * blockDim.x + threadIdx.x;
    float4 v = in[i];
    v.x = __uint_as_float(f2t(v.x));
    v.y = __uint_as_float(f2t(v.y));
    v.z = __uint_as_float(f2t(v.z));
    v.w = __uint_as_float(f2t(v.w));
    outp[i] = v;
}

// ---------------------------------------------------------------------------
// tf32 GEMM via mma.sync, cp.async double-buffered. Tile 128x128, BK=32.
// Operands are pre-rounded tf32 bit patterns: NO cvt in the hot loop.
// Smem (dynamic 71680B): As[2][128][36] then Bs[2][32][136] (floats).
// MODE 0: A=g_x, B=g_wk[N=3072], scatter k/q/v rounded (q * 0.125).
// MODE 1: A=g_y (pre-rounded), B=g_wp[N=1024], fp32 out + bias.
// ---------------------------------------------------------------------------
template <int MODE>
__global__ __launch_bounds__(256, 2) void gemm_k(const float* __restrict__ bias,
                                                 float* __restrict__ out) {
    constexpr int Kd = NC;
    extern __shared__ __align__(16) float sm[];
    const float* Ap = (MODE == 0) ? g_x : g_y;
    const float* Bw = (MODE == 0) ? g_wk : g_wp;
    const int N = (MODE == 0) ? 3 * NC : NC;

    int tid = threadIdx.x, warp = tid >> 5, lane = tid & 31;
    int g = lane >> 2, t = lane & 3;
    int wm = warp >> 2, wn = warp & 3;
    int m0 = blockIdx.y * 128, n0 = blockIdx.x * 128;
    uint32_t sbase = smem_u32(sm);

    float acc[4][4][4];
#pragma unroll
    for (int mi = 0; mi < 4; mi++)
#pragma unroll
        for (int ni = 0; ni < 4; ni++)
#pragma unroll
            for (int e = 0; e < 4; e++) acc[mi][ni][e] = 0.0f;

    auto fill = [&](int kt, int buf) {
        const float* asrc = Ap + (size_t)m0 * Kd + kt * 32;
        uint32_t abase = sbase + buf * 4608 * 4;
#pragma unroll
        for (int p = 0; p < 4; p++) {
            int idx = tid + p * 256;
            int r = idx >> 3, ch = idx & 7;
            cp16(abase + r * 144 + ch * 16, asrc + (size_t)r * Kd + ch * 4);
        }
        const float* bsrc = Bw + (size_t)(kt * 32) * N + n0;
        uint32_t bbase = sbase + (9216 + buf * 4352) * 4;
#pragma unroll
        for (int p = 0; p < 4; p++) {
            int idx = tid + p * 256;
            int r = idx >> 5, ch = idx & 31;
            cp16(bbase + r * 544 + ch * 16, bsrc + (size_t)r * N + ch * 4);
        }
    };

    fill(0, 0);
    cp_commit();
    int buf = 0;
    for (int kt = 0; kt < 32; kt++) {
        if (kt + 1 < 32) fill(kt + 1, buf ^ 1);
        cp_commit();
        cp_wait<1>();
        __syncthreads();

        const uint32_t* Au = (const uint32_t*)(sm + buf * 4608);
        const uint32_t* Bu = (const uint32_t*)(sm + 9216 + buf * 4352);
#pragma unroll
        for (int kk = 0; kk < 4; kk++) {
            int k0 = kk * 8;
            uint32_t af[4][4];
#pragma unroll
            for (int mi = 0; mi < 4; mi++) {
                int r = wm * 64 + mi * 16 + g;
                af[mi][0] = Au[r * 36 + k0 + t];
                af[mi][1] = Au[(r + 8) * 36 + k0 + t];
                af[mi][2] = Au[r * 36 + k0 + t + 4];
                af[mi][3] = Au[(r + 8) * 36 + k0 + t + 4];
            }
            uint32_t bf[4][2];
#pragma unroll
            for (int ni = 0; ni < 4; ni++) {
                int c = wn * 32 + ni * 8 + g;
                bf[ni][0] = Bu[(k0 + t) * 136 + c];
                bf[ni][1] = Bu[(k0 + t + 4) * 136 + c];
            }
#pragma unroll
            for (int mi = 0; mi < 4; mi++)
#pragma unroll
                for (int ni = 0; ni < 4; ni++)
                    mma8(acc[mi][ni], af[mi], bf[ni][0], bf[ni][1]);
        }
        __syncthreads();
        buf ^= 1;
    }

    // Epilogue. C frag: c0=(g,2t), c1=(g,2t+1), c2=(g+8,2t), c3=(g+8,2t+1)
#pragma unroll
    for (int mi = 0; mi < 4; mi++)
#pragma unroll
        for (int ni = 0; ni < 4; ni++)
#pragma unroll
            for (int e = 0; e < 4; e++) {
                int m = m0 + wm * 64 + mi * 16 + g + ((e >= 2) ? 8 : 0);
                int n = n0 + wn * 32 + ni * 8 + t * 2 + (e & 1);
                float val = acc[mi][ni][e] + bias[n];
                if (MODE == 0) {
                    int b = m >> 11, tt = m & (NT - 1);
                    int head = n / 192;
                    int r = n - head * 192;
                    int kind = r >> 6, d = r & 63;   // split order: k, q, v
                    size_t idx = ((size_t)(b * NH + head) * NT + tt) * DH + d;
                    if (kind == 0)
                        g_k[idx] = __uint_as_float(f2t(val));
                    else if (kind == 1)
                        g_q[idx] = __uint_as_float(f2t(val * 0.125f));
                    else
                        g_v[idx] = __uint_as_float(f2t(val));
                } else {
                    out[(size_t)m * NC + n] = val;
                }
            }
}

// ---------------------------------------------------------------------------
// Causal flash attention, cp.async double-buffered. Grid (T/64, B*H), 4 warps.
// k/q/v pre-rounded tf32 bits: no cvt on Q/K/V reads; cvt only on P.
// Smem (dynamic 71680B floats): Ks[2][64][68] then Vs[2][64][72].
// ---------------------------------------------------------------------------
__global__ __launch_bounds__(128, 3) void attn_k() {
    extern __shared__ __align__(16) float sm[];
    int tid = threadIdx.x, w = tid >> 5, lane = tid & 31;
    int g = lane >> 2, t = lane & 3;
    int bh = blockIdx.y;
    int qb = blockIdx.x;
    size_t base = (size_t)bh * NT * DH;
    int r0 = qb * 64 + w * 16;
    uint32_t sbase = smem_u32(sm);

    // Q fragments: raw rounded bits
    uint32_t qf[8][4];
    const uint32_t* qp = (const uint32_t*)(g_q + base + (size_t)r0 * DH);
#pragma unroll
    for (int kk = 0; kk < 8; kk++) {
        qf[kk][0] = qp[g * DH + kk * 8 + t];
        qf[kk][1] = qp[(g + 8) * DH + kk * 8 + t];
        qf[kk][2] = qp[g * DH + kk * 8 + t + 4];
        qf[kk][3] = qp[(g + 8) * DH + kk * 8 + t + 4];
    }

    float o[8][4];
#pragma unroll
    for (int jd = 0; jd < 8; jd++)
#pragma unroll
        for (int e = 0; e < 4; e++) o[jd][e] = 0.0f;
    float mrow[2] = {-1e30f, -1e30f};
    float lrow[2] = {0.0f, 0.0f};

    const unsigned FULL = 0xffffffffu;
    int s1 = (lane & ~3) | (t >> 1);
    int s2 = s1 + 2;

    // K/V tile = 64 rows x 64 floats = 64x16 16B-chunks = 1024 cp16 each.
    // 128 threads x 8 iters: r = idx>>4 in [0,64), ch = idx&15 in [0,16).
    auto fill = [&](int kt, int buf) {
        const float* kp = g_k + base + (size_t)kt * 64 * DH;
        const float* vp = g_v + base + (size_t)kt * 64 * DH;
#pragma unroll
        for (int p = 0; p < 8; p++) {
            int idx = tid + p * 128;
            int r = idx >> 4, ch = idx & 15;
            cp16(sbase + buf * 17408 + r * 272 + ch * 16, kp + r * DH + ch * 4);
            cp16(sbase + 2 * 17408 + buf * 18432 + r * 288 + ch * 16,
                 vp + r * DH + ch * 4);
        }
    };

    fill(0, 0);
    cp_commit();
    int buf = 0;
    for (int kt = 0; kt <= qb; kt++) {
        if (kt + 1 <= qb) fill(kt + 1, buf ^ 1);
        cp_commit();
        cp_wait<1>();
        __syncthreads();

        const uint32_t* Ku = (const uint32_t*)(sm + buf * 4352);
        const uint32_t* Vu = (const uint32_t*)(sm + 8704 + buf * 4608);

        // S = Q K^T
        float s[8][4];
#pragma unroll
        for (int j = 0; j < 8; j++)
#pragma unroll
            for (int e = 0; e < 4; e++) s[j][e] = 0.0f;
#pragma unroll
        for (int kk = 0; kk < 8; kk++) {
#pragma unroll
            for (int j = 0; j < 8; j++) {
                uint32_t b0 = Ku[(j * 8 + g) * 68 + kk * 8 + t];
                uint32_t b1 = Ku[(j * 8 + g) * 68 + kk * 8 + t + 4];
                mma8(s[j], qf[kk], b0, b1);
            }
        }

        if (kt == qb) {
#pragma unroll
            for (int j = 0; j < 8; j++) {
                int key = kt * 64 + j * 8 + t * 2;
                if (key > r0 + g)         s[j][0] = -1e30f;
                if (key + 1 > r0 + g)     s[j][1] = -1e30f;
                if (key > r0 + g + 8)     s[j][2] = -1e30f;
                if (key + 1 > r0 + g + 8) s[j][3] = -1e30f;
            }
        }

#pragma unroll
        for (int h2 = 0; h2 < 2; h2++) {
            float tm = -1e30f;
#pragma unroll
            for (int j = 0; j < 8; j++)
                tm = fmaxf(tm, fmaxf(s[j][h2 * 2], s[j][h2 * 2 + 1]));
            tm = fmaxf(tm, __shfl_xor_sync(FULL, tm, 1));
            tm = fmaxf(tm, __shfl_xor_sync(FULL, tm, 2));
            float nm = fmaxf(mrow[h2], tm);
            float corr = __expf(mrow[h2] - nm);
            mrow[h2] = nm;
            float sum = 0.0f;
#pragma unroll
            for (int j = 0; j < 8; j++) {
                float p0 = __expf(s[j][h2 * 2] - nm);
                float p1 = __expf(s[j][h2 * 2 + 1] - nm);
                s[j][h2 * 2] = p0; s[j][h2 * 2 + 1] = p1;
                sum += p0 + p1;
            }
            sum += __shfl_xor_sync(FULL, sum, 1);
            sum += __shfl_xor_sync(FULL, sum, 2);
            lrow[h2] = lrow[h2] * corr + sum;
#pragma unroll
            for (int jd = 0; jd < 8; jd++) {
                o[jd][h2 * 2] *= corr;
                o[jd][h2 * 2 + 1] *= corr;
            }
        }

        // O += P V (P re-fragmented via quad shuffles, cvt to tf32)
        bool odd = (t & 1);
#pragma unroll
        for (int kk = 0; kk < 8; kk++) {
            float c0 = s[kk][0], c1 = s[kk][1], c2 = s[kk][2], c3 = s[kk][3];
            float v0a = __shfl_sync(FULL, c0, s1), v0b = __shfl_sync(FULL, c1, s1);
            float v1a = __shfl_sync(FULL, c2, s1), v1b = __shfl_sync(FULL, c3, s1);
            float v2a = __shfl_sync(FULL, c0, s2), v2b = __shfl_sync(FULL, c1, s2);
            float v3a = __shfl_sync(FULL, c2, s2), v3b = __shfl_sync(FULL, c3, s2);
            uint32_t pa[4];
            pa[0] = f2t(odd ? v0b : v0a);
            pa[1] = f2t(odd ? v1b : v1a);
            pa[2] = f2t(odd ? v2b : v2a);
            pa[3] = f2t(odd ? v3b : v3a);
#pragma unroll
            for (int jd = 0; jd < 8; jd++) {
                uint32_t b0 = Vu[(kk * 8 + t) * 72 + jd * 8 + g];
                uint32_t b1 = Vu[(kk * 8 + t + 4) * 72 + jd * 8 + g];
                mma8(o[jd], pa, b0, b1);
            }
        }
        __syncthreads();
        buf ^= 1;
    }

    // Normalize, round to tf32 bits (proj GEMM consumes raw), write y
    int b = bh >> 4, head = bh & 15;
    float inv0 = 1.0f / lrow[0], inv1 = 1.0f / lrow[1];
#pragma unroll
    for (int jd = 0; jd < 8; jd++) {
        int d = head * 64 + jd * 8 + t * 2;
        float* y0 = g_y + (size_t)(b * NT + r0 + g) * NC + d;
        float* y1 = g_y + (size_t)(b * NT + r0 + g + 8) * NC + d;
        y0[0] = __uint_as_float(f2t(o[jd][0] * inv0));
        y0[1] = __uint_as_float(f2t(o[jd][1] * inv0));
        y1[0] = __uint_as_float(f2t(o[jd][2] * inv1));
        y1[1] = __uint_as_float(f2t(o[jd][3] * inv1));
    }
}

// ---------------------------------------------------------------------------
extern "C" void kernel_launch(void* const* d_in, const int* in_sizes, int n_in,
                              void* d_out, int out_size) {
    (void)in_sizes; (void)n_in; (void)out_size;
    const float* x      = (const float*)d_in[0];
    // d_in[1] = att_mask: causal tril by construction; masking is hardcoded.
    const float* w_kqv  = (const float*)d_in[2];
    const float* b_kqv  = (const float*)d_in[3];
    const float* w_proj = (const float*)d_in[4];
    const float* b_proj = (const float*)d_in[5];
    float* out = (float*)d_out;

    cudaFuncSetAttribute(gemm_k<0>, cudaFuncAttributeMaxDynamicSharedMemorySize, 71680);
    cudaFuncSetAttribute(gemm_k<1>, cudaFuncAttributeMaxDynamicSharedMemorySize, 71680);
    cudaFuncSetAttribute(attn_k, cudaFuncAttributeMaxDynamicSharedMemorySize, 71680);

    // prep: tf32-round inputs/weights (bits become direct mma operands)
    round_k<0><<<4096, 256>>>((const float4*)x);
    round_k<1><<<3072, 256>>>((const float4*)w_kqv);
    round_k<2><<<1024, 256>>>((const float4*)w_proj);
    // 1) kqv = x @ w_kqv + b -> k/q/v scratch (q pre-scaled, all rounded)
    gemm_k<0><<<dim3(24, 32), 256, 71680>>>(b_kqv, nullptr);
    // 2) causal flash attention -> g_y (rounded)
    attn_k<<<dim3(NT / 64, NB * NH), 128, 71680>>>();
    // 3) out = y @ w_proj + b
    gemm_k<1><<<dim3(8, 32), 256, 71680>>>(b_proj, out);
}

// round 6
// speedup vs baseline: 2.3842x; 1.8810x over previous
#include <cuda_runtime.h>
#include <cuda_fp16.h>
#include <cstdint>

#define NB 2
#define NT 2048
#define NC 1024
#define NH 16
#define DH 64

// scratch (device globals: no allocation in kernel_launch)
__device__ __align__(16) __half g_q[NB * NH * NT * DH];
__device__ __align__(16) __half g_k[NB * NH * NT * DH];
__device__ __align__(16) __half g_v[NB * NH * NT * DH];
__device__ __align__(16) __half g_y[NB * NT * NC];
__device__ __align__(16) __half g_x[NB * NT * NC];       // fp16 x
__device__ __align__(16) __half g_wk[3 * NC * NC];       // w_kqv^T [3072][1024]
__device__ __align__(16) __half g_wp[NC * NC];           // w_proj^T [1024][1024]

__device__ __forceinline__ uint32_t smem_u32(const void* p) {
    uint32_t a;
    asm("{ .reg .u64 t; cvta.to.shared.u64 t, %1; cvt.u32.u64 %0, t; }"
        : "=r"(a) : "l"(p));
    return a;
}

__device__ __forceinline__ void cp16(uint32_t dst, const void* src) {
    asm volatile("cp.async.cg.shared.global [%0], [%1], 16;\n" :: "r"(dst), "l"(src));
}
__device__ __forceinline__ void cp_commit() {
    asm volatile("cp.async.commit_group;\n" ::: "memory");
}
template <int N>
__device__ __forceinline__ void cp_wait() {
    asm volatile("cp.async.wait_group %0;\n" :: "n"(N) : "memory");
}

__device__ __forceinline__ void ldsm4(uint32_t& r0, uint32_t& r1, uint32_t& r2,
                                      uint32_t& r3, uint32_t addr) {
    asm volatile("ldmatrix.sync.aligned.m8n8.x4.shared.b16 {%0,%1,%2,%3}, [%4];"
                 : "=r"(r0), "=r"(r1), "=r"(r2), "=r"(r3) : "r"(addr));
}
__device__ __forceinline__ void ldsm4t(uint32_t& r0, uint32_t& r1, uint32_t& r2,
                                       uint32_t& r3, uint32_t addr) {
    asm volatile("ldmatrix.sync.aligned.m8n8.x4.trans.shared.b16 {%0,%1,%2,%3}, [%4];"
                 : "=r"(r0), "=r"(r1), "=r"(r2), "=r"(r3) : "r"(addr));
}

__device__ __forceinline__ void mma16(float d[4], const uint32_t a[4],
                                      uint32_t b0, uint32_t b1) {
    asm volatile(
        "mma.sync.aligned.m16n8k16.row.col.f32.f16.f16.f32 "
        "{%0,%1,%2,%3}, {%4,%5,%6,%7}, {%8,%9}, {%0,%1,%2,%3};\n"
        : "+f"(d[0]), "+f"(d[1]), "+f"(d[2]), "+f"(d[3])
        : "r"(a[0]), "r"(a[1]), "r"(a[2]), "r"(a[3]), "r"(b0), "r"(b1));
}

__device__ __forceinline__ uint32_t packh2(float lo, float hi) {
    __half2 h = __floats2half2_rn(lo, hi);
    return *(uint32_t*)&h;
}

// ---------------------------------------------------------------------------
// Prep: x -> fp16; weights -> transposed fp16 ([n][k] K-major).
// ---------------------------------------------------------------------------
__global__ void cvtx_k(const float4* __restrict__ in) {
    int i = blockIdx.x * blockDim.x + threadIdx.x;
    float4 v = in[i];
    ((__half2*)g_x)[2 * i]     = __floats2half2_rn(v.x, v.y);
    ((__half2*)g_x)[2 * i + 1] = __floats2half2_rn(v.z, v.w);
}

template <int T>
__global__ void transw_k(const float* __restrict__ W, int cols) {
    __half* outT = (T == 0) ? g_wk : g_wp;
    __shared__ float t[32][33];
    int bx = blockIdx.x * 32, by = blockIdx.y * 32;
    int tx = threadIdx.x, ty = threadIdx.y;
#pragma unroll
    for (int i = 0; i < 32; i += 8)
        t[ty + i][tx] = W[(size_t)(by + ty + i) * cols + bx + tx];
    __syncthreads();
#pragma unroll
    for (int i = 0; i < 32; i += 8)
        outT[(size_t)(bx + ty + i) * NC + by + tx] = __float2half_rn(t[tx][ty + i]);
}

// ---------------------------------------------------------------------------
// fp16 GEMM (m16n8k16), cp.async double-buffered, ldmatrix fragments.
// A [m][k] and B [n][k] both K-major halves. Tile 128x128, BK=64.
// Smem halves: A[2][128][72] then B[2][128][72]  (73728 B total).
// MODE 0: A=g_x, B=g_wk, scatter k/q/v halves (q*0.125).
// MODE 1: A=g_y, B=g_wp, fp32 out + bias.
// ---------------------------------------------------------------------------
template <int MODE>
__global__ __launch_bounds__(256, 2) void gemm_k(const float* __restrict__ bias,
                                                 float* __restrict__ out) {
    extern __shared__ __align__(16) __half sm[];
    const __half* Ap = (MODE == 0) ? g_x : g_y;
    const __half* Bw = (MODE == 0) ? g_wk : g_wp;

    int tid = threadIdx.x, warp = tid >> 5, lane = tid & 31;
    int g = lane >> 2, t = lane & 3;
    int wm = warp >> 2, wn = warp & 3;
    int m0 = blockIdx.y * 128, n0 = blockIdx.x * 128;
    uint32_t sbase = smem_u32(sm);

    float acc[4][4][4];
#pragma unroll
    for (int mi = 0; mi < 4; mi++)
#pragma unroll
        for (int ni = 0; ni < 4; ni++)
#pragma unroll
            for (int e = 0; e < 4; e++) acc[mi][ni][e] = 0.0f;

    // tile = 128 rows x 64 halves = 128 x 8 cp16 = 1024 cp16 each for A and B
    auto fill = [&](int kt, int buf) {
        const __half* asrc = Ap + (size_t)m0 * NC + kt * 64;
        const __half* bsrc = Bw + (size_t)n0 * NC + kt * 64;
        uint32_t ab = sbase + buf * 18432;
        uint32_t bb = sbase + 36864 + buf * 18432;
#pragma unroll
        for (int p = 0; p < 4; p++) {
            int idx = tid + p * 256;
            int r = idx >> 3, ch = idx & 7;
            cp16(ab + r * 144 + ch * 16, asrc + (size_t)r * NC + ch * 8);
        }
#pragma unroll
        for (int p = 0; p < 4; p++) {
            int idx = tid + p * 256;
            int r = idx >> 3, ch = idx & 7;
            cp16(bb + r * 144 + ch * 16, bsrc + (size_t)r * NC + ch * 8);
        }
    };

    fill(0, 0);
    cp_commit();
    int buf = 0;
    for (int kt = 0; kt < 16; kt++) {
        if (kt + 1 < 16) fill(kt + 1, buf ^ 1);
        cp_commit();
        cp_wait<1>();
        __syncthreads();

        uint32_t abase = sbase + buf * 18432;
        uint32_t bbase = sbase + 36864 + buf * 18432;
#pragma unroll
        for (int kk = 0; kk < 4; kk++) {
            uint32_t a[4][4];
#pragma unroll
            for (int mi = 0; mi < 4; mi++) {
                int row = wm * 64 + mi * 16 + (lane & 15);
                int c16 = kk * 2 + (lane >> 4);
                ldsm4(a[mi][0], a[mi][1], a[mi][2], a[mi][3],
                      abase + row * 144 + c16 * 16);
            }
            uint32_t b[4][2];
#pragma unroll
            for (int np = 0; np < 2; np++) {
                int row = wn * 32 + np * 16 + ((lane >> 4) & 1) * 8 + (lane & 7);
                int c16 = kk * 2 + ((lane >> 3) & 1);
                uint32_t r0, r1, r2, r3;
                ldsm4(r0, r1, r2, r3, bbase + row * 144 + c16 * 16);
                b[np * 2][0] = r0;     b[np * 2][1] = r1;
                b[np * 2 + 1][0] = r2; b[np * 2 + 1][1] = r3;
            }
#pragma unroll
            for (int mi = 0; mi < 4; mi++)
#pragma unroll
                for (int ni = 0; ni < 4; ni++)
                    mma16(acc[mi][ni], a[mi], b[ni][0], b[ni][1]);
        }
        __syncthreads();
        buf ^= 1;
    }

    // Epilogue. C frag: c0=(g,2t), c1=(g,2t+1), c2=(g+8,2t), c3=(g+8,2t+1)
#pragma unroll
    for (int mi = 0; mi < 4; mi++)
#pragma unroll
        for (int ni = 0; ni < 4; ni++)
#pragma unroll
            for (int e = 0; e < 4; e++) {
                int m = m0 + wm * 64 + mi * 16 + g + ((e >= 2) ? 8 : 0);
                int n = n0 + wn * 32 + ni * 8 + t * 2 + (e & 1);
                float val = acc[mi][ni][e] + bias[n];
                if (MODE == 0) {
                    int b = m >> 11, tt = m & (NT - 1);
                    int head = n / 192;
                    int r = n - head * 192;
                    int kind = r >> 6, d = r & 63;   // split order: k, q, v
                    size_t idx = ((size_t)(b * NH + head) * NT + tt) * DH + d;
                    if (kind == 0)
                        g_k[idx] = __float2half_rn(val);
                    else if (kind == 1)
                        g_q[idx] = __float2half_rn(val * 0.125f);
                    else
                        g_v[idx] = __float2half_rn(val);
                } else {
                    out[(size_t)m * NC + n] = val;
                }
            }
}

// ---------------------------------------------------------------------------
// Causal flash attention, fp16 mma, cp.async double-buffered.
// Grid (T/64, B*H), 4 warps. K,V tiles [64 keys][72-pad halves] in smem.
// QK: B-frags via ldmatrix from K[key][d]. PV: B-frags via ldmatrix.trans
// from V[key][d]; P packs straight from S C-frags (no shuffles).
// ---------------------------------------------------------------------------
__global__ __launch_bounds__(128, 3) void attn_k() {
    extern __shared__ __align__(16) __half sm[];
    int tid = threadIdx.x, w = tid >> 5, lane = tid & 31;
    int g = lane >> 2, t = lane & 3;
    int bh = blockIdx.y;
    int qb = blockIdx.x;
    size_t base = (size_t)bh * NT * DH;
    int r0 = qb * 64 + w * 16;
    uint32_t sbase = smem_u32(sm);

    // Q A-frags (q pre-scaled by 1/8): a0=(g,2t), a1=(g+8,2t), a2=(g,2t+8), a3
    uint32_t qf[4][4];
    const __half* qp = g_q + base + (size_t)r0 * DH;
#pragma unroll
    for (int kk = 0; kk < 4; kk++) {
        qf[kk][0] = *(const uint32_t*)&qp[g * DH + 16 * kk + 2 * t];
        qf[kk][1] = *(const uint32_t*)&qp[(g + 8) * DH + 16 * kk + 2 * t];
        qf[kk][2] = *(const uint32_t*)&qp[g * DH + 16 * kk + 2 * t + 8];
        qf[kk][3] = *(const uint32_t*)&qp[(g + 8) * DH + 16 * kk + 2 * t + 8];
    }

    float o[8][4];
#pragma unroll
    for (int jd = 0; jd < 8; jd++)
#pragma unroll
        for (int e = 0; e < 4; e++) o[jd][e] = 0.0f;
    float mrow[2] = {-1e30f, -1e30f};
    float lrow[2] = {0.0f, 0.0f};
    const unsigned FULL = 0xffffffffu;

    // tile = 64 rows x 64 halves = 64 x 8 cp16 = 512 each; 4 per thread
    auto fill = [&](int kt, int buf) {
        const __half* kp = g_k + base + (size_t)kt * 64 * DH;
        const __half* vp = g_v + base + (size_t)kt * 64 * DH;
#pragma unroll
        for (int p = 0; p < 4; p++) {
            int idx = tid + p * 128;
            int r = idx >> 3, ch = idx & 7;
            cp16(sbase + buf * 9216 + r * 144 + ch * 16, kp + r * DH + ch * 8);
            cp16(sbase + 18432 + buf * 9216 + r * 144 + ch * 16, vp + r * DH + ch * 8);
        }
    };

    fill(0, 0);
    cp_commit();
    int buf = 0;
    for (int kt = 0; kt <= qb; kt++) {
        if (kt + 1 <= qb) fill(kt + 1, buf ^ 1);
        cp_commit();
        cp_wait<1>();
        __syncthreads();

        uint32_t kbase = sbase + buf * 9216;
        uint32_t vbase = sbase + 18432 + buf * 9216;

        // S = Q K^T : 8 key n-blocks x 4 d k-steps
        float s[8][4];
#pragma unroll
        for (int j = 0; j < 8; j++)
#pragma unroll
            for (int e = 0; e < 4; e++) s[j][e] = 0.0f;
#pragma unroll
        for (int kk = 0; kk < 4; kk++) {
#pragma unroll
            for (int jp = 0; jp < 4; jp++) {
                int row = jp * 16 + ((lane >> 4) & 1) * 8 + (lane & 7);
                int c16 = kk * 2 + ((lane >> 3) & 1);
                uint32_t b0, b1, b2, b3;
                ldsm4(b0, b1, b2, b3, kbase + row * 144 + c16 * 16);
                mma16(s[jp * 2], qf[kk], b0, b1);
                mma16(s[jp * 2 + 1], qf[kk], b2, b3);
            }
        }

        // causal mask: only diagonal tile partial
        if (kt == qb) {
#pragma unroll
            for (int j = 0; j < 8; j++) {
                int key = kt * 64 + j * 8 + t * 2;
                if (key > r0 + g)         s[j][0] = -1e30f;
                if (key + 1 > r0 + g)     s[j][1] = -1e30f;
                if (key > r0 + g + 8)     s[j][2] = -1e30f;
                if (key + 1 > r0 + g + 8) s[j][3] = -1e30f;
            }
        }

        // online softmax per row-half
#pragma unroll
        for (int h2 = 0; h2 < 2; h2++) {
            float tm = -1e30f;
#pragma unroll
            for (int j = 0; j < 8; j++)
                tm = fmaxf(tm, fmaxf(s[j][h2 * 2], s[j][h2 * 2 + 1]));
            tm = fmaxf(tm, __shfl_xor_sync(FULL, tm, 1));
            tm = fmaxf(tm, __shfl_xor_sync(FULL, tm, 2));
            float nm = fmaxf(mrow[h2], tm);
            float corr = __expf(mrow[h2] - nm);
            mrow[h2] = nm;
            float sum = 0.0f;
#pragma unroll
            for (int j = 0; j < 8; j++) {
                float p0 = __expf(s[j][h2 * 2] - nm);
                float p1 = __expf(s[j][h2 * 2 + 1] - nm);
                s[j][h2 * 2] = p0; s[j][h2 * 2 + 1] = p1;
                sum += p0 + p1;
            }
            sum += __shfl_xor_sync(FULL, sum, 1);
            sum += __shfl_xor_sync(FULL, sum, 2);
            lrow[h2] = lrow[h2] * corr + sum;
#pragma unroll
            for (int jd = 0; jd < 8; jd++) {
                o[jd][h2 * 2] *= corr;
                o[jd][h2 * 2 + 1] *= corr;
            }
        }

        // O += P V : P A-frags pack directly from S C-frags (no shuffles)
#pragma unroll
        for (int kk2 = 0; kk2 < 4; kk2++) {
            uint32_t pa[4];
            pa[0] = packh2(s[2 * kk2][0], s[2 * kk2][1]);
            pa[1] = packh2(s[2 * kk2][2], s[2 * kk2][3]);
            pa[2] = packh2(s[2 * kk2 + 1][0], s[2 * kk2 + 1][1]);
            pa[3] = packh2(s[2 * kk2 + 1][2], s[2 * kk2 + 1][3]);
#pragma unroll
            for (int jdp = 0; jdp < 4; jdp++) {
                int row = kk2 * 16 + ((lane >> 3) & 1) * 8 + (lane & 7);
                int c16 = jdp * 2 + ((lane >> 4) & 1);
                uint32_t b0, b1, b2, b3;
                ldsm4t(b0, b1, b2, b3, vbase + row * 144 + c16 * 16);
                mma16(o[jdp * 2], pa, b0, b1);
                mma16(o[jdp * 2 + 1], pa, b2, b3);
            }
        }
        __syncthreads();
        buf ^= 1;
    }

    // normalize, write y halves
    int b = bh >> 4, head = bh & 15;
    float inv0 = 1.0f / lrow[0], inv1 = 1.0f / lrow[1];
#pragma unroll
    for (int jd = 0; jd < 8; jd++) {
        int d = head * 64 + jd * 8 + t * 2;
        *(__half2*)&g_y[(size_t)(b * NT + r0 + g) * NC + d] =
            __floats2half2_rn(o[jd][0] * inv0, o[jd][1] * inv0);
        *(__half2*)&g_y[(size_t)(b * NT + r0 + g + 8) * NC + d] =
            __floats2half2_rn(o[jd][2] * inv1, o[jd][3] * inv1);
    }
}

// ---------------------------------------------------------------------------
extern "C" void kernel_launch(void* const* d_in, const int* in_sizes, int n_in,
                              void* d_out, int out_size) {
    (void)in_sizes; (void)n_in; (void)out_size;
    const float* x      = (const float*)d_in[0];
    // d_in[1] = att_mask: causal tril by construction; masking is hardcoded.
    const float* w_kqv  = (const float*)d_in[2];
    const float* b_kqv  = (const float*)d_in[3];
    const float* w_proj = (const float*)d_in[4];
    const float* b_proj = (const float*)d_in[5];
    float* out = (float*)d_out;

    cudaFuncSetAttribute(gemm_k<0>, cudaFuncAttributeMaxDynamicSharedMemorySize, 73728);
    cudaFuncSetAttribute(gemm_k<1>, cudaFuncAttributeMaxDynamicSharedMemorySize, 73728);
    cudaFuncSetAttribute(attn_k, cudaFuncAttributeMaxDynamicSharedMemorySize, 36864);

    // prep: fp16 inputs; weights transposed to [n][k]
    cvtx_k<<<4096, 256>>>((const float4*)x);
    transw_k<0><<<dim3(96, 32), dim3(32, 8)>>>(w_kqv, 3 * NC);
    transw_k<1><<<dim3(32, 32), dim3(32, 8)>>>(w_proj, NC);
    // 1) kqv = x @ w_kqv + b -> k/q/v halves (q pre-scaled)
    gemm_k<0><<<dim3(24, 32), 256, 73728>>>(b_kqv, nullptr);
    // 2) causal flash attention -> g_y halves
    attn_k<<<dim3(NT / 64, NB * NH), 128, 36864>>>();
    // 3) out = y @ w_proj + b
    gemm_k<1><<<dim3(8, 32), 256, 73728>>>(b_proj, out);
}

// round 7
// speedup vs baseline: 2.5027x; 1.0497x over previous
#include <cuda_runtime.h>
#include <cuda_fp16.h>
#include <cstdint>

#define NB 2
#define NT 2048
#define NC 1024
#define NH 16
#define DH 64

// scratch (device globals: no allocation in kernel_launch)
__device__ __align__(16) __half g_q[NB * NH * NT * DH];
__device__ __align__(16) __half g_k[NB * NH * NT * DH];
__device__ __align__(16) __half g_v[NB * NH * NT * DH];
__device__ __align__(16) __half g_y[NB * NT * NC];
__device__ __align__(16) __half g_x[NB * NT * NC];       // fp16 x
__device__ __align__(16) __half g_wk[3 * NC * NC];       // w_kqv^T [3072][1024]
__device__ __align__(16) __half g_wp[NC * NC];           // w_proj^T [1024][1024]

__device__ __forceinline__ uint32_t smem_u32(const void* p) {
    uint32_t a;
    asm("{ .reg .u64 t; cvta.to.shared.u64 t, %1; cvt.u32.u64 %0, t; }"
        : "=r"(a) : "l"(p));
    return a;
}

__device__ __forceinline__ void cp16(uint32_t dst, const void* src) {
    asm volatile("cp.async.cg.shared.global [%0], [%1], 16;\n" :: "r"(dst), "l"(src));
}
__device__ __forceinline__ void cp_commit() {
    asm volatile("cp.async.commit_group;\n" ::: "memory");
}
template <int N>
__device__ __forceinline__ void cp_wait() {
    asm volatile("cp.async.wait_group %0;\n" :: "n"(N) : "memory");
}

__device__ __forceinline__ void ldsm4(uint32_t& r0, uint32_t& r1, uint32_t& r2,
                                      uint32_t& r3, uint32_t addr) {
    asm volatile("ldmatrix.sync.aligned.m8n8.x4.shared.b16 {%0,%1,%2,%3}, [%4];"
                 : "=r"(r0), "=r"(r1), "=r"(r2), "=r"(r3) : "r"(addr));
}
__device__ __forceinline__ void ldsm4t(uint32_t& r0, uint32_t& r1, uint32_t& r2,
                                       uint32_t& r3, uint32_t addr) {
    asm volatile("ldmatrix.sync.aligned.m8n8.x4.trans.shared.b16 {%0,%1,%2,%3}, [%4];"
                 : "=r"(r0), "=r"(r1), "=r"(r2), "=r"(r3) : "r"(addr));
}

__device__ __forceinline__ void mma16(float d[4], const uint32_t a[4],
                                      uint32_t b0, uint32_t b1) {
    asm volatile(
        "mma.sync.aligned.m16n8k16.row.col.f32.f16.f16.f32 "
        "{%0,%1,%2,%3}, {%4,%5,%6,%7}, {%8,%9}, {%0,%1,%2,%3};\n"
        : "+f"(d[0]), "+f"(d[1]), "+f"(d[2]), "+f"(d[3])
        : "r"(a[0]), "r"(a[1]), "r"(a[2]), "r"(a[3]), "r"(b0), "r"(b1));
}

__device__ __forceinline__ uint32_t packh2(float lo, float hi) {
    __half2 h = __floats2half2_rn(lo, hi);
    return *(uint32_t*)&h;
}

// ---------------------------------------------------------------------------
// Prep: x -> fp16; weights -> transposed fp16 ([n][k] K-major).
// ---------------------------------------------------------------------------
__global__ void cvtx_k(const float4* __restrict__ in) {
    int i = blockIdx.x * blockDim.x + threadIdx.x;
    float4 v = in[i];
    ((__half2*)g_x)[2 * i]     = __floats2half2_rn(v.x, v.y);
    ((__half2*)g_x)[2 * i + 1] = __floats2half2_rn(v.z, v.w);
}

template <int T>
__global__ void transw_k(const float* __restrict__ W, int cols) {
    __half* outT = (T == 0) ? g_wk : g_wp;
    __shared__ float t[32][33];
    int bx = blockIdx.x * 32, by = blockIdx.y * 32;
    int tx = threadIdx.x, ty = threadIdx.y;
#pragma unroll
    for (int i = 0; i < 32; i += 8)
        t[ty + i][tx] = W[(size_t)(by + ty + i) * cols + bx + tx];
    __syncthreads();
#pragma unroll
    for (int i = 0; i < 32; i += 8)
        outT[(size_t)(bx + ty + i) * NC + by + tx] = __float2half_rn(t[tx][ty + i]);
}

// ---------------------------------------------------------------------------
// fp16 GEMM (m16n8k16), 3-stage cp.async ring, ONE barrier per K-iteration.
// A [m][k], B [n][k] K-major halves. Tile 128x128, BK=64, 16 iterations.
// Smem: 3 stages x (A 128x144B + B 128x144B) = 110592 B.
// MODE 0: A=g_x, B=g_wk, scatter k/q/v halves (q*0.125).
// MODE 1: A=g_y, B=g_wp, fp32 out + bias.
// ---------------------------------------------------------------------------
template <int MODE>
__global__ __launch_bounds__(256, 2) void gemm_k(const float* __restrict__ bias,
                                                 float* __restrict__ out) {
    extern __shared__ __align__(16) __half sm[];
    const __half* Ap = (MODE == 0) ? g_x : g_y;
    const __half* Bw = (MODE == 0) ? g_wk : g_wp;

    int tid = threadIdx.x, warp = tid >> 5, lane = tid & 31;
    int g = lane >> 2, t = lane & 3;
    int wm = warp >> 2, wn = warp & 3;
    int m0 = blockIdx.y * 128, n0 = blockIdx.x * 128;
    uint32_t sbase = smem_u32(sm);

    float acc[4][4][4];
#pragma unroll
    for (int mi = 0; mi < 4; mi++)
#pragma unroll
        for (int ni = 0; ni < 4; ni++)
#pragma unroll
            for (int e = 0; e < 4; e++) acc[mi][ni][e] = 0.0f;

    // stage tile: A/B each 128 rows x 64 halves = 1024 cp16
    auto fill = [&](int kt, int s) {
        const __half* asrc = Ap + (size_t)m0 * NC + kt * 64;
        const __half* bsrc = Bw + (size_t)n0 * NC + kt * 64;
        uint32_t ab = sbase + s * 36864;
        uint32_t bb = ab + 18432;
#pragma unroll
        for (int p = 0; p < 4; p++) {
            int idx = tid + p * 256;
            int r = idx >> 3, ch = idx & 7;
            cp16(ab + r * 144 + ch * 16, asrc + (size_t)r * NC + ch * 8);
        }
#pragma unroll
        for (int p = 0; p < 4; p++) {
            int idx = tid + p * 256;
            int r = idx >> 3, ch = idx & 7;
            cp16(bb + r * 144 + ch * 16, bsrc + (size_t)r * NC + ch * 8);
        }
    };

    fill(0, 0); cp_commit();
    fill(1, 1); cp_commit();

    int s = 0;
    for (int kt = 0; kt < 16; kt++) {
        cp_wait<1>();
        __syncthreads();

        uint32_t abase = sbase + s * 36864;
        uint32_t bbase = abase + 18432;
#pragma unroll
        for (int kk = 0; kk < 4; kk++) {
            uint32_t a[4][4];
#pragma unroll
            for (int mi = 0; mi < 4; mi++) {
                int row = wm * 64 + mi * 16 + (lane & 15);
                int c16 = kk * 2 + (lane >> 4);
                ldsm4(a[mi][0], a[mi][1], a[mi][2], a[mi][3],
                      abase + row * 144 + c16 * 16);
            }
            uint32_t b[4][2];
#pragma unroll
            for (int np = 0; np < 2; np++) {
                int row = wn * 32 + np * 16 + ((lane >> 4) & 1) * 8 + (lane & 7);
                int c16 = kk * 2 + ((lane >> 3) & 1);
                uint32_t r0, r1, r2, r3;
                ldsm4(r0, r1, r2, r3, bbase + row * 144 + c16 * 16);
                b[np * 2][0] = r0;     b[np * 2][1] = r1;
                b[np * 2 + 1][0] = r2; b[np * 2 + 1][1] = r3;
            }
#pragma unroll
            for (int mi = 0; mi < 4; mi++)
#pragma unroll
                for (int ni = 0; ni < 4; ni++)
                    mma16(acc[mi][ni], a[mi], b[ni][0], b[ni][1]);
        }

        if (kt + 2 < 16) {
            int sn = s + 2; if (sn >= 3) sn -= 3;
            fill(kt + 2, sn);
        }
        cp_commit();
        if (++s == 3) s = 0;
    }

    // Epilogue. C frag: c0=(g,2t), c1=(g,2t+1), c2=(g+8,2t), c3=(g+8,2t+1)
#pragma unroll
    for (int mi = 0; mi < 4; mi++)
#pragma unroll
        for (int ni = 0; ni < 4; ni++)
#pragma unroll
            for (int e = 0; e < 4; e++) {
                int m = m0 + wm * 64 + mi * 16 + g + ((e >= 2) ? 8 : 0);
                int n = n0 + wn * 32 + ni * 8 + t * 2 + (e & 1);
                float val = acc[mi][ni][e] + bias[n];
                if (MODE == 0) {
                    int b = m >> 11, tt = m & (NT - 1);
                    int head = n / 192;
                    int r = n - head * 192;
                    int kind = r >> 6, d = r & 63;   // split order: k, q, v
                    size_t idx = ((size_t)(b * NH + head) * NT + tt) * DH + d;
                    if (kind == 0)
                        g_k[idx] = __float2half_rn(val);
                    else if (kind == 1)
                        g_q[idx] = __float2half_rn(val * 0.125f);
                    else
                        g_v[idx] = __float2half_rn(val);
                } else {
                    out[(size_t)m * NC + n] = val;
                }
            }
}

// ---------------------------------------------------------------------------
// Causal flash attention, fp16 mma, 3-stage cp.async ring, one barrier/iter.
// Grid (T/64, B*H), 4 warps. Stage = K[64][72] + V[64][72] halves = 18432 B.
// ---------------------------------------------------------------------------
__global__ __launch_bounds__(128, 3) void attn_k() {
    extern __shared__ __align__(16) __half sm[];
    int tid = threadIdx.x, w = tid >> 5, lane = tid & 31;
    int g = lane >> 2, t = lane & 3;
    int bh = blockIdx.y;
    int qb = blockIdx.x;
    size_t base = (size_t)bh * NT * DH;
    int r0 = qb * 64 + w * 16;
    uint32_t sbase = smem_u32(sm);

    // Q A-frags (q pre-scaled by 1/8)
    uint32_t qf[4][4];
    const __half* qp = g_q + base + (size_t)r0 * DH;
#pragma unroll
    for (int kk = 0; kk < 4; kk++) {
        qf[kk][0] = *(const uint32_t*)&qp[g * DH + 16 * kk + 2 * t];
        qf[kk][1] = *(const uint32_t*)&qp[(g + 8) * DH + 16 * kk + 2 * t];
        qf[kk][2] = *(const uint32_t*)&qp[g * DH + 16 * kk + 2 * t + 8];
        qf[kk][3] = *(const uint32_t*)&qp[(g + 8) * DH + 16 * kk + 2 * t + 8];
    }

    float o[8][4];
#pragma unroll
    for (int jd = 0; jd < 8; jd++)
#pragma unroll
        for (int e = 0; e < 4; e++) o[jd][e] = 0.0f;
    float mrow[2] = {-1e30f, -1e30f};
    float lrow[2] = {0.0f, 0.0f};
    const unsigned FULL = 0xffffffffu;

    // stage tile: K,V each 64 rows x 64 halves = 512 cp16; 4 per thread each
    auto fill = [&](int kt, int s) {
        const __half* kp = g_k + base + (size_t)kt * 64 * DH;
        const __half* vp = g_v + base + (size_t)kt * 64 * DH;
        uint32_t kb = sbase + s * 18432;
        uint32_t vb = kb + 9216;
#pragma unroll
        for (int p = 0; p < 4; p++) {
            int idx = tid + p * 128;
            int r = idx >> 3, ch = idx & 7;
            cp16(kb + r * 144 + ch * 16, kp + r * DH + ch * 8);
            cp16(vb + r * 144 + ch * 16, vp + r * DH + ch * 8);
        }
    };

    fill(0, 0); cp_commit();
    if (qb >= 1) fill(1, 1);
    cp_commit();

    int s = 0;
    for (int kt = 0; kt <= qb; kt++) {
        cp_wait<1>();
        __syncthreads();

        uint32_t kbase = sbase + s * 18432;
        uint32_t vbase = kbase + 9216;

        // S = Q K^T
        float sc[8][4];
#pragma unroll
        for (int j = 0; j < 8; j++)
#pragma unroll
            for (int e = 0; e < 4; e++) sc[j][e] = 0.0f;
#pragma unroll
        for (int kk = 0; kk < 4; kk++) {
#pragma unroll
            for (int jp = 0; jp < 4; jp++) {
                int row = jp * 16 + ((lane >> 4) & 1) * 8 + (lane & 7);
                int c16 = kk * 2 + ((lane >> 3) & 1);
                uint32_t b0, b1, b2, b3;
                ldsm4(b0, b1, b2, b3, kbase + row * 144 + c16 * 16);
                mma16(sc[jp * 2], qf[kk], b0, b1);
                mma16(sc[jp * 2 + 1], qf[kk], b2, b3);
            }
        }

        // causal mask: only diagonal tile partial
        if (kt == qb) {
#pragma unroll
            for (int j = 0; j < 8; j++) {
                int key = kt * 64 + j * 8 + t * 2;
                if (key > r0 + g)         sc[j][0] = -1e30f;
                if (key + 1 > r0 + g)     sc[j][1] = -1e30f;
                if (key > r0 + g + 8)     sc[j][2] = -1e30f;
                if (key + 1 > r0 + g + 8) sc[j][3] = -1e30f;
            }
        }

        // online softmax per row-half
#pragma unroll
        for (int h2 = 0; h2 < 2; h2++) {
            float tm = -1e30f;
#pragma unroll
            for (int j = 0; j < 8; j++)
                tm = fmaxf(tm, fmaxf(sc[j][h2 * 2], sc[j][h2 * 2 + 1]));
            tm = fmaxf(tm, __shfl_xor_sync(FULL, tm, 1));
            tm = fmaxf(tm, __shfl_xor_sync(FULL, tm, 2));
            float nm = fmaxf(mrow[h2], tm);
            float corr = __expf(mrow[h2] - nm);
            mrow[h2] = nm;
            float sum = 0.0f;
#pragma unroll
            for (int j = 0; j < 8; j++) {
                float p0 = __expf(sc[j][h2 * 2] - nm);
                float p1 = __expf(sc[j][h2 * 2 + 1] - nm);
                sc[j][h2 * 2] = p0; sc[j][h2 * 2 + 1] = p1;
                sum += p0 + p1;
            }
            sum += __shfl_xor_sync(FULL, sum, 1);
            sum += __shfl_xor_sync(FULL, sum, 2);
            lrow[h2] = lrow[h2] * corr + sum;
#pragma unroll
            for (int jd = 0; jd < 8; jd++) {
                o[jd][h2 * 2] *= corr;
                o[jd][h2 * 2 + 1] *= corr;
            }
        }

        // O += P V : P A-frags pack directly from S C-frags (no shuffles)
#pragma unroll
        for (int kk2 = 0; kk2 < 4; kk2++) {
            uint32_t pa[4];
            pa[0] = packh2(sc[2 * kk2][0], sc[2 * kk2][1]);
            pa[1] = packh2(sc[2 * kk2][2], sc[2 * kk2][3]);
            pa[2] = packh2(sc[2 * kk2 + 1][0], sc[2 * kk2 + 1][1]);
            pa[3] = packh2(sc[2 * kk2 + 1][2], sc[2 * kk2 + 1][3]);
#pragma unroll
            for (int jdp = 0; jdp < 4; jdp++) {
                int row = kk2 * 16 + ((lane >> 3) & 1) * 8 + (lane & 7);
                int c16 = jdp * 2 + ((lane >> 4) & 1);
                uint32_t b0, b1, b2, b3;
                ldsm4t(b0, b1, b2, b3, vbase + row * 144 + c16 * 16);
                mma16(o[jdp * 2], pa, b0, b1);
                mma16(o[jdp * 2 + 1], pa, b2, b3);
            }
        }

        if (kt + 2 <= qb) {
            int sn = s + 2; if (sn >= 3) sn -= 3;
            fill(kt + 2, sn);
        }
        cp_commit();
        if (++s == 3) s = 0;
    }

    // normalize, write y halves
    int b = bh >> 4, head = bh & 15;
    float inv0 = 1.0f / lrow[0], inv1 = 1.0f / lrow[1];
#pragma unroll
    for (int jd = 0; jd < 8; jd++) {
        int d = head * 64 + jd * 8 + t * 2;
        *(__half2*)&g_y[(size_t)(b * NT + r0 + g) * NC + d] =
            __floats2half2_rn(o[jd][0] * inv0, o[jd][1] * inv0);
        *(__half2*)&g_y[(size_t)(b * NT + r0 + g + 8) * NC + d] =
            __floats2half2_rn(o[jd][2] * inv1, o[jd][3] * inv1);
    }
}

// ---------------------------------------------------------------------------
extern "C" void kernel_launch(void* const* d_in, const int* in_sizes, int n_in,
                              void* d_out, int out_size) {
    (void)in_sizes; (void)n_in; (void)out_size;
    const float* x      = (const float*)d_in[0];
    // d_in[1] = att_mask: causal tril by construction; masking is hardcoded.
    const float* w_kqv  = (const float*)d_in[2];
    const float* b_kqv  = (const float*)d_in[3];
    const float* w_proj = (const float*)d_in[4];
    const float* b_proj = (const float*)d_in[5];
    float* out = (float*)d_out;

    cudaFuncSetAttribute(gemm_k<0>, cudaFuncAttributeMaxDynamicSharedMemorySize, 110592);
    cudaFuncSetAttribute(gemm_k<1>, cudaFuncAttributeMaxDynamicSharedMemorySize, 110592);
    cudaFuncSetAttribute(attn_k, cudaFuncAttributeMaxDynamicSharedMemorySize, 55296);

    // prep: fp16 inputs; weights transposed to [n][k]
    cvtx_k<<<4096, 256>>>((const float4*)x);
    transw_k<0><<<dim3(96, 32), dim3(32, 8)>>>(w_kqv, 3 * NC);
    transw_k<1><<<dim3(32, 32), dim3(32, 8)>>>(w_proj, NC);
    // 1) kqv = x @ w_kqv + b -> k/q/v halves (q pre-scaled)
    gemm_k<0><<<dim3(24, 32), 256, 110592>>>(b_kqv, nullptr);
    // 2) causal flash attention -> g_y halves
    attn_k<<<dim3(NT / 64, NB * NH), 128, 55296>>>();
    // 3) out = y @ w_proj + b
    gemm_k<1><<<dim3(8, 32), 256, 110592>>>(b_proj, out);
}

// round 8
// speedup vs baseline: 2.5501x; 1.0190x over previous
#include <cuda_runtime.h>
#include <cuda_fp16.h>
#include <cstdint>

#define NB 2
#define NT 2048
#define NC 1024
#define NH 16
#define DH 64

// scratch (device globals: no allocation in kernel_launch)
__device__ __align__(16) __half g_q[NB * NH * NT * DH];
__device__ __align__(16) __half g_k[NB * NH * NT * DH];
__device__ __align__(16) __half g_v[NB * NH * NT * DH];
__device__ __align__(16) __half g_y[NB * NT * NC];
__device__ __align__(16) __half g_x[NB * NT * NC];       // fp16 x           [m][k]
__device__ __align__(16) __half g_wk[3 * NC * NC];       // fp16 w_kqv       [k][n=3072]
__device__ __align__(16) __half g_wp[NC * NC];           // fp16 w_proj      [k][n=1024]

__device__ __forceinline__ uint32_t smem_u32(const void* p) {
    uint32_t a;
    asm("{ .reg .u64 t; cvta.to.shared.u64 t, %1; cvt.u32.u64 %0, t; }"
        : "=r"(a) : "l"(p));
    return a;
}

__device__ __forceinline__ void cp16(uint32_t dst, const void* src) {
    asm volatile("cp.async.cg.shared.global [%0], [%1], 16;\n" :: "r"(dst), "l"(src));
}
__device__ __forceinline__ void cp_commit() {
    asm volatile("cp.async.commit_group;\n" ::: "memory");
}
template <int N>
__device__ __forceinline__ void cp_wait() {
    asm volatile("cp.async.wait_group %0;\n" :: "n"(N) : "memory");
}

__device__ __forceinline__ void ldsm4(uint32_t& r0, uint32_t& r1, uint32_t& r2,
                                      uint32_t& r3, uint32_t addr) {
    asm volatile("ldmatrix.sync.aligned.m8n8.x4.shared.b16 {%0,%1,%2,%3}, [%4];"
                 : "=r"(r0), "=r"(r1), "=r"(r2), "=r"(r3) : "r"(addr));
}
__device__ __forceinline__ void ldsm4t(uint32_t& r0, uint32_t& r1, uint32_t& r2,
                                       uint32_t& r3, uint32_t addr) {
    asm volatile("ldmatrix.sync.aligned.m8n8.x4.trans.shared.b16 {%0,%1,%2,%3}, [%4];"
                 : "=r"(r0), "=r"(r1), "=r"(r2), "=r"(r3) : "r"(addr));
}

__device__ __forceinline__ void mma16(float d[4], const uint32_t a[4],
                                      uint32_t b0, uint32_t b1) {
    asm volatile(
        "mma.sync.aligned.m16n8k16.row.col.f32.f16.f16.f32 "
        "{%0,%1,%2,%3}, {%4,%5,%6,%7}, {%8,%9}, {%0,%1,%2,%3};\n"
        : "+f"(d[0]), "+f"(d[1]), "+f"(d[2]), "+f"(d[3])
        : "r"(a[0]), "r"(a[1]), "r"(a[2]), "r"(a[3]), "r"(b0), "r"(b1));
}

__device__ __forceinline__ uint32_t packh2(float lo, float hi) {
    __half2 h = __floats2half2_rn(lo, hi);
    return *(uint32_t*)&h;
}

// ---------------------------------------------------------------------------
// Fused prep: fp32 -> fp16, layouts unchanged. x: 1048576 float4,
// w_kqv: 786432 float4, w_proj: 262144 float4. Grid 8192 x 256.
// ---------------------------------------------------------------------------
__global__ void prep_k(const float4* __restrict__ x, const float4* __restrict__ wk,
                       const float4* __restrict__ wp) {
    int i = blockIdx.x * blockDim.x + threadIdx.x;
    const float4* src;
    __half2* dst;
    int li;
    if (i < 1048576) {
        src = x; li = i; dst = (__half2*)g_x;
    } else if (i < 1048576 + 786432) {
        src = wk; li = i - 1048576; dst = (__half2*)g_wk;
    } else {
        src = wp; li = i - 1835008; dst = (__half2*)g_wp;
    }
    float4 v = src[li];
    dst[2 * li]     = __floats2half2_rn(v.x, v.y);
    dst[2 * li + 1] = __floats2half2_rn(v.z, v.w);
}

// ---------------------------------------------------------------------------
// fp16 GEMM (m16n8k16). A [m][k], B [k][n] (native layout, ldmatrix.trans).
// Tile 128x128, BK=64, 3-stage cp.async ring, fragment double-buffer in kk.
// Smem/stage: A 128x144B (18432) + B 64x272B (17408) = 35840 B; x3 = 107520.
// MODE 0: A=g_x, B=g_wk (N=3072), scatter k/q/v halves (q*0.125).
// MODE 1: A=g_y, B=g_wp (N=1024), fp32 out + bias.
// ---------------------------------------------------------------------------
template <int MODE>
__global__ __launch_bounds__(256, 2) void gemm_k(const float* __restrict__ bias,
                                                 float* __restrict__ out) {
    extern __shared__ __align__(16) __half sm[];
    const __half* Ap = (MODE == 0) ? g_x : g_y;
    const __half* Bw = (MODE == 0) ? g_wk : g_wp;
    const int N = (MODE == 0) ? 3 * NC : NC;

    int tid = threadIdx.x, warp = tid >> 5, lane = tid & 31;
    int g = lane >> 2, t = lane & 3;
    int wm = warp >> 2, wn = warp & 3;
    int m0 = blockIdx.y * 128, n0 = blockIdx.x * 128;
    uint32_t sbase = smem_u32(sm);

    float acc[4][4][4];
#pragma unroll
    for (int mi = 0; mi < 4; mi++)
#pragma unroll
        for (int ni = 0; ni < 4; ni++)
#pragma unroll
            for (int e = 0; e < 4; e++) acc[mi][ni][e] = 0.0f;

    // A: 128 rows x 8 chunks; B: 64 rows x 16 chunks (both 1024 cp16)
    auto fill = [&](int kt, int s) {
        const __half* asrc = Ap + (size_t)m0 * NC + kt * 64;
        const __half* bsrc = Bw + (size_t)(kt * 64) * N + n0;
        uint32_t ab = sbase + s * 35840;
        uint32_t bb = ab + 18432;
#pragma unroll
        for (int p = 0; p < 4; p++) {
            int idx = tid + p * 256;
            int r = idx >> 3, ch = idx & 7;
            cp16(ab + r * 144 + ch * 16, asrc + (size_t)r * NC + ch * 8);
        }
#pragma unroll
        for (int p = 0; p < 4; p++) {
            int idx = tid + p * 256;
            int r = idx >> 4, ch = idx & 15;
            cp16(bb + r * 272 + ch * 16, bsrc + (size_t)r * N + ch * 8);
        }
    };

    fill(0, 0); cp_commit();
    fill(1, 1); cp_commit();

    int s = 0;
    for (int kt = 0; kt < 16; kt++) {
        cp_wait<1>();
        __syncthreads();

        uint32_t abase = sbase + s * 35840;
        uint32_t bbase = abase + 18432;

        uint32_t a[2][4][4], b[2][2][4];
        auto loadA = [&](int kk, uint32_t (&ar)[4][4]) {
#pragma unroll
            for (int mi = 0; mi < 4; mi++) {
                int row = wm * 64 + mi * 16 + (lane & 15);
                int c16 = kk * 2 + (lane >> 4);
                ldsm4(ar[mi][0], ar[mi][1], ar[mi][2], ar[mi][3],
                      abase + row * 144 + c16 * 16);
            }
        };
        auto loadB = [&](int kk, uint32_t (&br)[2][4]) {
#pragma unroll
            for (int np = 0; np < 2; np++) {
                int row = kk * 16 + ((lane >> 3) & 1) * 8 + (lane & 7);
                int c16 = wn * 4 + np * 2 + ((lane >> 4) & 1);
                ldsm4t(br[np][0], br[np][1], br[np][2], br[np][3],
                       bbase + row * 272 + c16 * 16);
            }
        };

        loadA(0, a[0]);
        loadB(0, b[0]);
#pragma unroll
        for (int kk = 0; kk < 4; kk++) {
            int cur = kk & 1;
            if (kk < 3) {
                loadA(kk + 1, a[cur ^ 1]);
                loadB(kk + 1, b[cur ^ 1]);
            }
#pragma unroll
            for (int mi = 0; mi < 4; mi++)
#pragma unroll
                for (int np = 0; np < 2; np++) {
                    mma16(acc[mi][np * 2], a[cur][mi], b[cur][np][0], b[cur][np][1]);
                    mma16(acc[mi][np * 2 + 1], a[cur][mi], b[cur][np][2], b[cur][np][3]);
                }
        }

        if (kt + 2 < 16) {
            int sn = s + 2; if (sn >= 3) sn -= 3;
            fill(kt + 2, sn);
        }
        cp_commit();
        if (++s == 3) s = 0;
    }

    // Epilogue. C frag: c0=(g,2t), c1=(g,2t+1), c2=(g+8,2t), c3=(g+8,2t+1)
#pragma unroll
    for (int mi = 0; mi < 4; mi++)
#pragma unroll
        for (int ni = 0; ni < 4; ni++)
#pragma unroll
            for (int e = 0; e < 4; e++) {
                int m = m0 + wm * 64 + mi * 16 + g + ((e >= 2) ? 8 : 0);
                int n = n0 + wn * 32 + ni * 8 + t * 2 + (e & 1);
                float val = acc[mi][ni][e] + bias[n];
                if (MODE == 0) {
                    int b = m >> 11, tt = m & (NT - 1);
                    int head = n / 192;
                    int r = n - head * 192;
                    int kind = r >> 6, d = r & 63;   // split order: k, q, v
                    size_t idx = ((size_t)(b * NH + head) * NT + tt) * DH + d;
                    if (kind == 0)
                        g_k[idx] = __float2half_rn(val);
                    else if (kind == 1)
                        g_q[idx] = __float2half_rn(val * 0.125f);
                    else
                        g_v[idx] = __float2half_rn(val);
                } else {
                    out[(size_t)m * NC + n] = val;
                }
            }
}

// ---------------------------------------------------------------------------
// Causal flash attention, fp16 mma, 3-stage cp.async ring, occupancy 4.
// Grid (T/64, B*H); qb REVERSED so heavy diagonal CTAs launch first.
// Stage = K[64][72] + V[64][72] halves = 18432 B; x3 = 55296.
// ---------------------------------------------------------------------------
__global__ __launch_bounds__(128, 4) void attn_k() {
    extern __shared__ __align__(16) __half sm[];
    int tid = threadIdx.x, w = tid >> 5, lane = tid & 31;
    int g = lane >> 2, t = lane & 3;
    int bh = blockIdx.y;
    int qb = gridDim.x - 1 - blockIdx.x;       // heavy tiles first
    size_t base = (size_t)bh * NT * DH;
    int r0 = qb * 64 + w * 16;
    uint32_t sbase = smem_u32(sm);

    // Q A-frags (q pre-scaled by 1/8)
    uint32_t qf[4][4];
    const __half* qp = g_q + base + (size_t)r0 * DH;
#pragma unroll
    for (int kk = 0; kk < 4; kk++) {
        qf[kk][0] = *(const uint32_t*)&qp[g * DH + 16 * kk + 2 * t];
        qf[kk][1] = *(const uint32_t*)&qp[(g + 8) * DH + 16 * kk + 2 * t];
        qf[kk][2] = *(const uint32_t*)&qp[g * DH + 16 * kk + 2 * t + 8];
        qf[kk][3] = *(const uint32_t*)&qp[(g + 8) * DH + 16 * kk + 2 * t + 8];
    }

    float o[8][4];
#pragma unroll
    for (int jd = 0; jd < 8; jd++)
#pragma unroll
        for (int e = 0; e < 4; e++) o[jd][e] = 0.0f;
    float mrow[2] = {-1e30f, -1e30f};
    float lrow[2] = {0.0f, 0.0f};
    const unsigned FULL = 0xffffffffu;

    auto fill = [&](int kt, int s) {
        const __half* kp = g_k + base + (size_t)kt * 64 * DH;
        const __half* vp = g_v + base + (size_t)kt * 64 * DH;
        uint32_t kb = sbase + s * 18432;
        uint32_t vb = kb + 9216;
#pragma unroll
        for (int p = 0; p < 4; p++) {
            int idx = tid + p * 128;
            int r = idx >> 3, ch = idx & 7;
            cp16(kb + r * 144 + ch * 16, kp + r * DH + ch * 8);
            cp16(vb + r * 144 + ch * 16, vp + r * DH + ch * 8);
        }
    };

    fill(0, 0); cp_commit();
    if (qb >= 1) fill(1, 1);
    cp_commit();

    int s = 0;
    for (int kt = 0; kt <= qb; kt++) {
        cp_wait<1>();
        __syncthreads();

        uint32_t kbase = sbase + s * 18432;
        uint32_t vbase = kbase + 9216;

        // S = Q K^T
        float sc[8][4];
#pragma unroll
        for (int j = 0; j < 8; j++)
#pragma unroll
            for (int e = 0; e < 4; e++) sc[j][e] = 0.0f;
#pragma unroll
        for (int kk = 0; kk < 4; kk++) {
#pragma unroll
            for (int jp = 0; jp < 4; jp++) {
                int row = jp * 16 + ((lane >> 4) & 1) * 8 + (lane & 7);
                int c16 = kk * 2 + ((lane >> 3) & 1);
                uint32_t b0, b1, b2, b3;
                ldsm4(b0, b1, b2, b3, kbase + row * 144 + c16 * 16);
                mma16(sc[jp * 2], qf[kk], b0, b1);
                mma16(sc[jp * 2 + 1], qf[kk], b2, b3);
            }
        }

        // causal mask: only diagonal tile partial
        if (kt == qb) {
#pragma unroll
            for (int j = 0; j < 8; j++) {
                int key = kt * 64 + j * 8 + t * 2;
                if (key > r0 + g)         sc[j][0] = -1e30f;
                if (key + 1 > r0 + g)     sc[j][1] = -1e30f;
                if (key > r0 + g + 8)     sc[j][2] = -1e30f;
                if (key + 1 > r0 + g + 8) sc[j][3] = -1e30f;
            }
        }

        // online softmax per row-half
#pragma unroll
        for (int h2 = 0; h2 < 2; h2++) {
            float tm = -1e30f;
#pragma unroll
            for (int j = 0; j < 8; j++)
                tm = fmaxf(tm, fmaxf(sc[j][h2 * 2], sc[j][h2 * 2 + 1]));
            tm = fmaxf(tm, __shfl_xor_sync(FULL, tm, 1));
            tm = fmaxf(tm, __shfl_xor_sync(FULL, tm, 2));
            float nm = fmaxf(mrow[h2], tm);
            float corr = __expf(mrow[h2] - nm);
            mrow[h2] = nm;
            float sum = 0.0f;
#pragma unroll
            for (int j = 0; j < 8; j++) {
                float p0 = __expf(sc[j][h2 * 2] - nm);
                float p1 = __expf(sc[j][h2 * 2 + 1] - nm);
                sc[j][h2 * 2] = p0; sc[j][h2 * 2 + 1] = p1;
                sum += p0 + p1;
            }
            sum += __shfl_xor_sync(FULL, sum, 1);
            sum += __shfl_xor_sync(FULL, sum, 2);
            lrow[h2] = lrow[h2] * corr + sum;
#pragma unroll
            for (int jd = 0; jd < 8; jd++) {
                o[jd][h2 * 2] *= corr;
                o[jd][h2 * 2 + 1] *= corr;
            }
        }

        // O += P V : P A-frags pack directly from S C-frags (no shuffles)
#pragma unroll
        for (int kk2 = 0; kk2 < 4; kk2++) {
            uint32_t pa[4];
            pa[0] = packh2(sc[2 * kk2][0], sc[2 * kk2][1]);
            pa[1] = packh2(sc[2 * kk2][2], sc[2 * kk2][3]);
            pa[2] = packh2(sc[2 * kk2 + 1][0], sc[2 * kk2 + 1][1]);
            pa[3] = packh2(sc[2 * kk2 + 1][2], sc[2 * kk2 + 1][3]);
#pragma unroll
            for (int jdp = 0; jdp < 4; jdp++) {
                int row = kk2 * 16 + ((lane >> 3) & 1) * 8 + (lane & 7);
                int c16 = jdp * 2 + ((lane >> 4) & 1);
                uint32_t b0, b1, b2, b3;
                ldsm4t(b0, b1, b2, b3, vbase + row * 144 + c16 * 16);
                mma16(o[jdp * 2], pa, b0, b1);
                mma16(o[jdp * 2 + 1], pa, b2, b3);
            }
        }

        if (kt + 2 <= qb) {
            int sn = s + 2; if (sn >= 3) sn -= 3;
            fill(kt + 2, sn);
        }
        cp_commit();
        if (++s == 3) s = 0;
    }

    // normalize, write y halves
    int b = bh >> 4, head = bh & 15;
    float inv0 = 1.0f / lrow[0], inv1 = 1.0f / lrow[1];
#pragma unroll
    for (int jd = 0; jd < 8; jd++) {
        int d = head * 64 + jd * 8 + t * 2;
        *(__half2*)&g_y[(size_t)(b * NT + r0 + g) * NC + d] =
            __floats2half2_rn(o[jd][0] * inv0, o[jd][1] * inv0);
        *(__half2*)&g_y[(size_t)(b * NT + r0 + g + 8) * NC + d] =
            __floats2half2_rn(o[jd][2] * inv1, o[jd][3] * inv1);
    }
}

// ---------------------------------------------------------------------------
extern "C" void kernel_launch(void* const* d_in, const int* in_sizes, int n_in,
                              void* d_out, int out_size) {
    (void)in_sizes; (void)n_in; (void)out_size;
    const float* x      = (const float*)d_in[0];
    // d_in[1] = att_mask: causal tril by construction; masking is hardcoded.
    const float* w_kqv  = (const float*)d_in[2];
    const float* b_kqv  = (const float*)d_in[3];
    const float* w_proj = (const float*)d_in[4];
    const float* b_proj = (const float*)d_in[5];
    float* out = (float*)d_out;

    cudaFuncSetAttribute(gemm_k<0>, cudaFuncAttributeMaxDynamicSharedMemorySize, 107520);
    cudaFuncSetAttribute(gemm_k<1>, cudaFuncAttributeMaxDynamicSharedMemorySize, 107520);
    cudaFuncSetAttribute(attn_k, cudaFuncAttributeMaxDynamicSharedMemorySize, 55296);

    // prep: fp32 -> fp16, one fused launch (layouts unchanged)
    prep_k<<<8192, 256>>>((const float4*)x, (const float4*)w_kqv,
                          (const float4*)w_proj);
    // 1) kqv = x @ w_kqv + b -> k/q/v halves (q pre-scaled)
    gemm_k<0><<<dim3(24, 32), 256, 107520>>>(b_kqv, nullptr);
    // 2) causal flash attention -> g_y halves
    attn_k<<<dim3(NT / 64, NB * NH), 128, 55296>>>();
    // 3) out = y @ w_proj + b
    gemm_k<1><<<dim3(8, 32), 256, 107520>>>(b_proj, out);
}